// round 13
// baseline (speedup 1.0000x reference)
#include <cuda_runtime.h>
#include <cuda_fp16.h>
#include <stdint.h>
#include <math.h>

#define NB 148

// ---------------- scratch (no allocations allowed) ----------------
__device__ float g_y[512];                  // channel means
__device__ float g_A[32 * 32];              // gaussian matrix A[i][x]
__device__ float g_f0t[1024 * 512];         // f0 transposed: [pix][ch]
__device__ float g_sigt[1024 * 512];        // sigmoid(f0): [pix][ch]
__device__ __half g_Wh[512 * 1024];         // W fp16 hi
__device__ __half g_Wl[512 * 1024];         // W fp16 residual
__device__ __half g_ch[1024 * 1024];        // cat fp16 hi, natural flat [i][p]
__device__ __half g_cl[1024 * 1024];        // cat fp16 residual
__device__ float g_z1[512 * 1024];          // split-K half-1 partial
__device__ unsigned g_arrive[8];            // grid barrier tickets (monotonic)

// ---------------- helpers ----------------
__device__ __forceinline__ uint32_t smem_u32(const void* p) {
    uint32_t a;
    asm("{ .reg .u64 t; cvta.to.shared.u64 t, %1; cvt.u32.u64 %0, t; }" : "=r"(a) : "l"(p));
    return a;
}
#define CPA16(sm, g) asm volatile("cp.async.ca.shared.global [%0], [%1], 16;" :: "r"(sm), "l"(g))
#define CPA_COMMIT()  asm volatile("cp.async.commit_group;" ::: "memory")
#define CPA_WAIT0()   asm volatile("cp.async.wait_group 0;" ::: "memory")
#define LDMX4(r, a) \
    asm volatile("ldmatrix.sync.aligned.m8n8.x4.shared.b16 {%0,%1,%2,%3}, [%4];" \
                 : "=r"((r)[0]), "=r"((r)[1]), "=r"((r)[2]), "=r"((r)[3]) : "r"(a))
#define LDMX4T(r, a) \
    asm volatile("ldmatrix.sync.aligned.m8n8.x4.trans.shared.b16 {%0,%1,%2,%3}, [%4];" \
                 : "=r"((r)[0]), "=r"((r)[1]), "=r"((r)[2]), "=r"((r)[3]) : "r"(a))
#define MMA16(d, a, b0v, b1v) \
    asm volatile("mma.sync.aligned.m16n8k16.row.col.f32.f16.f16.f32 " \
                 "{%0,%1,%2,%3},{%4,%5,%6,%7},{%8,%9},{%0,%1,%2,%3};" \
                 : "+f"((d)[0]), "+f"((d)[1]), "+f"((d)[2]), "+f"((d)[3]) \
                 : "r"((a)[0]), "r"((a)[1]), "r"((a)[2]), "r"((a)[3]), "r"(b0v), "r"(b1v))

__device__ __forceinline__ void split_h(float f, __half& h, __half& l) {
    h = __float2half_rn(f);
    l = __float2half_rn(f - __half2float(h));
}

// GEMM smem geometry (same as R12)
#define AP 40
#define BP 72
#define A_PLANE (64 * AP)
#define B_PLANE (32 * BP)
#define ST_H (2 * A_PLANE + 2 * B_PLANE)   // 9728 halves / stage
#define OAH 0
#define OAL A_PLANE
#define OBH (2 * A_PLANE)
#define OBL (2 * A_PLANE + B_PLANE)

// grid barrier: monotonic tickets, replay-safe, no resets
__device__ __forceinline__ void gsync(int k) {
    __syncthreads();
    __threadfence();
    if (threadIdx.x == 0) {
        unsigned ticket = atomicAdd(&g_arrive[k], 1u);
        unsigned target = (ticket / NB + 1u) * NB;
        while (*(volatile unsigned*)&g_arrive[k] < target) { __nanosleep(64); }
    }
    __syncthreads();
    __threadfence();
}

__global__ void __launch_bounds__(256, 2) k_mega(
    const float* __restrict__ x,  const float* __restrict__ w1,
    const float* __restrict__ b1, const float* __restrict__ w2,
    const float* __restrict__ b2, const float* __restrict__ dw,
    float* __restrict__ out)
{
    __shared__ __align__(16) char u_smem[2 * ST_H * 2];   // 38912 B union buffer
    __shared__ float s_scale[512];
    __shared__ float s_hidden[32];
    __shared__ double s_srow[32];
    __shared__ float s_red[8], s_red2[8];
    __shared__ float s_wsum[8][9], s_sa[9];
    __shared__ float s_mean, s_inv;

    int t = threadIdx.x, bid = blockIdx.x;
    int lane = t & 31, w = t >> 5;

    // ================= P0: means (0-511) + gaussian A (512) + W split (513-1024)
    for (int job = bid; job < 1025; job += NB) {
        __syncthreads();
        if (job < 512) {
            int c = job;
            float4 v = ((const float4*)(x + c * 1024))[t];
            float s = v.x + v.y + v.z + v.w;
            #pragma unroll
            for (int o = 16; o; o >>= 1) s += __shfl_down_sync(0xffffffffu, s, o);
            if (lane == 0) s_red[w] = s;
            __syncthreads();
            if (t == 0) {
                float tot = 0.f;
                #pragma unroll
                for (int i = 0; i < 8; i++) tot += s_red[i];
                g_y[c] = tot * (1.f / 1024.f);
            }
        } else if (job == 512) {
            if (t < 32) {
                double s = 0.0;
                for (int xx = 0; xx < 32; xx++) {
                    double d = (double)(xx - t);
                    s += exp(-d * d / 4.5);
                }
                s_srow[t] = s;
            }
            __syncthreads();
            for (int idx = t; idx < 1024; idx += 256) {
                int i = idx >> 5, xx = idx & 31;
                double d = (double)(xx - i);
                g_A[idx] = (float)(exp(-d * d / 4.5) / s_srow[i]);
            }
        } else {
            int row = job - 513;   // 0..511
            #pragma unroll
            for (int j = 0; j < 4; j++) {
                int idx = row * 1024 + t + j * 256;
                __half h, l;
                split_h(dw[idx], h, l);
                g_Wh[idx] = h;
                g_Wl[idx] = l;
            }
        }
    }
    gsync(0);

    // ================= P1: SE MLP, redundantly per block -> s_scale (no barrier needed)
    {
        for (int u = w; u < 32; u += 8) {
            float a = 0.f;
            for (int c = lane; c < 512; c += 32) a += g_y[c] * w1[u * 512 + c];
            #pragma unroll
            for (int o = 16; o; o >>= 1) a += __shfl_down_sync(0xffffffffu, a, o);
            if (lane == 0) s_hidden[u] = fmaxf(a + b1[u], 0.f);
        }
        __syncthreads();
        for (int c = t; c < 512; c += 256) {
            float acc = b2[c];
            #pragma unroll
            for (int rr = 0; rr < 32; rr++) acc += s_hidden[rr] * w2[c * 32 + rr];
            s_scale[c] = 1.f / (1.f + expf(-acc));
        }
        __syncthreads();
    }

    // ================= P2: gauss (0-511) + scale/transpose/sigmoid (512-1023)
    for (int job = bid; job < 1024; job += NB) {
        __syncthreads();
        float* sbuf = (float*)u_smem;
        if (job < 512) {
            float* F   = sbuf;
            float* T   = sbuf + 1024;
            float* sA  = sbuf + 2048;
            float* sAt = sbuf + 3072;
            int c = job;
            float s = s_scale[c];
            for (int i = t; i < 1024; i += 256) {
                F[i] = x[c * 1024 + i] * s;
                float a = g_A[i];
                sA[i] = a;
                sAt[(i & 31) * 32 + (i >> 5)] = a;
            }
            __syncthreads();
            for (int idx = t; idx < 1024; idx += 256) {   // T[x][k] = sum_y A[k][y]*F[x][y]
                int xx = idx >> 5, k = idx & 31;
                float acc = 0.f;
                #pragma unroll
                for (int y = 0; y < 32; y++) acc += sAt[y * 32 + k] * F[xx * 32 + y];
                T[idx] = acc;
            }
            __syncthreads();
            for (int idx = t; idx < 1024; idx += 256) {   // B[i][k] = sum_x A[i][x]*T[x][k]
                int i = idx >> 5, k = idx & 31;
                float acc = 0.f;
                #pragma unroll
                for (int xx = 0; xx < 32; xx++) acc += sA[i * 32 + xx] * T[xx * 32 + k];
                int f = idx * 512 + c;
                __half h, l;
                split_h(acc, h, l);
                g_ch[f] = h;
                g_cl[f] = l;
            }
        } else {
            float (*tile)[33] = (float(*)[33])sbuf;
            int bid2 = job - 512;
            int p0 = (bid2 & 31) * 32, c0 = (bid2 >> 5) * 32;
            int tx = lane, ty = w;
            #pragma unroll
            for (int j = 0; j < 4; j++) {
                int ch = c0 + ty + j * 8;
                tile[ty + j * 8][tx] = x[ch * 1024 + p0 + tx] * s_scale[ch];
            }
            __syncthreads();
            #pragma unroll
            for (int j = 0; j < 4; j++) {
                int p = p0 + ty + j * 8;
                float v = tile[tx][ty + j * 8];
                g_f0t[p * 512 + c0 + tx] = v;
                g_sigt[p * 512 + c0 + tx] = 1.f / (1.f + expf(-v));
            }
        }
    }
    gsync(1);

    // ================= P3: 3x3 patch-correlation attention (R11 two-gather form)
    for (int pix = bid; pix < 1024; pix += NB) {
        __syncthreads();
        int pi = pix >> 5, pj = pix & 31;
        int base = pix * 512 + t;
        float sc0 = g_sigt[base];
        float sc1 = g_sigt[base + 256];
        bool okU = pi > 0, okD = pi < 31, okL = pj > 0, okR = pj < 31;
        bool ok[9];
        ok[0] = okU && okL; ok[1] = okU; ok[2] = okU && okR;
        ok[3] = okL;        ok[4] = true; ok[5] = okR;
        ok[6] = okD && okL; ok[7] = okD; ok[8] = okD && okR;
        const int off[9] = { -33*512, -32*512, -31*512, -1*512, 0, 1*512, 31*512, 32*512, 33*512 };
        float acc[9];
        #pragma unroll
        for (int uv = 0; uv < 9; uv++) {
            acc[uv] = ok[uv]
                ? sc0 * g_sigt[base + off[uv]] + sc1 * g_sigt[base + off[uv] + 256]
                : 0.f;
        }
        #pragma unroll
        for (int uv = 0; uv < 9; uv++)
            #pragma unroll
            for (int o = 16; o; o >>= 1) acc[uv] += __shfl_down_sync(0xffffffffu, acc[uv], o);
        if (lane == 0) {
            #pragma unroll
            for (int uv = 0; uv < 9; uv++) s_wsum[w][uv] = acc[uv];
        }
        __syncthreads();
        if (t < 32) {
            float v = -1e30f;
            if (t < 9) {
                float s2 = 0.f;
                #pragma unroll
                for (int ww = 0; ww < 8; ww++) s2 += s_wsum[ww][t];
                v = s2 * (1.f / 512.f);
            }
            float m = v;
            #pragma unroll
            for (int o = 16; o; o >>= 1) m = fmaxf(m, __shfl_xor_sync(0xffffffffu, m, o));
            float e = (t < 9) ? expf(v - m) : 0.f;
            float tot = e;
            #pragma unroll
            for (int o = 16; o; o >>= 1) tot += __shfl_xor_sync(0xffffffffu, tot, o);
            if (t < 9) s_sa[t] = e / tot;
        }
        __syncthreads();
        float o0 = 0.f, o1 = 0.f;
        #pragma unroll
        for (int uv = 0; uv < 9; uv++) {
            if (ok[uv]) {
                float a = s_sa[uv];
                o0 += a * g_f0t[base + off[uv]];
                o1 += a * g_f0t[base + off[uv] + 256];
            }
        }
        __half h, l;
        split_h(o0, h, l); g_ch[524288 + base] = h;       g_cl[524288 + base] = l;
        split_h(o1, h, l); g_ch[524288 + base + 256] = h; g_cl[524288 + base + 256] = l;
    }
    gsync(2);

    // ================= P4: GEMM tiles (fp16-split mma.sync, split-K=2, 256 tiles)
    {
        __half* sm = (__half*)u_smem;
        uint32_t smb = smem_u32(sm);
        int mbase = (w >> 1) * 16, nbase = (w & 1) * 32;
        int arow = t >> 2, aseg = t & 3;
        int brow = t >> 3, bseg = t & 7;
        uint32_t aDst = arow * (AP * 2) + aseg * 16;
        uint32_t bDst = brow * (BP * 2) + bseg * 16;
        int ar = lane & 7, ah8 = (lane >> 3) & 1, akh = lane >> 4;
        uint32_t aoffH = OAH * 2 + (mbase + ah8 * 8 + ar) * (AP * 2) + akh * 16;
        uint32_t aoffL = OAL * 2 + (mbase + ah8 * 8 + ar) * (AP * 2) + akh * 16;
        int br = lane & 7, bk8 = (lane >> 3) & 1, bn8 = lane >> 4;
        uint32_t boffH[2], boffL[2];
        #pragma unroll
        for (int ng = 0; ng < 2; ng++) {
            uint32_t col2 = (nbase + ng * 16 + bn8 * 8) * 2;
            boffH[ng] = OBH * 2 + (bk8 * 8 + br) * (BP * 2) + col2;
            boffL[ng] = OBL * 2 + (bk8 * 8 + br) * (BP * 2) + col2;
        }

        for (int tile = bid; tile < 256; tile += NB) {
            __syncthreads();   // guard smem reuse across tiles / phases
            int nx = tile & 15, my = (tile >> 4) & 7, kz = tile >> 7;
            int m0 = my * 64, n0 = nx * 64, kbase = kz * 512;
            const __half* aSrcH = g_Wh + (m0 + arow) * 1024 + kbase + aseg * 8;
            const __half* aSrcL = g_Wl + (m0 + arow) * 1024 + kbase + aseg * 8;
            const __half* bSrcH = g_ch + (kbase + brow) * 1024 + n0 + bseg * 8;
            const __half* bSrcL = g_cl + (kbase + brow) * 1024 + n0 + bseg * 8;

            float acc[4][4] = {};
            CPA16(smb + OAH * 2 + aDst, aSrcH);
            CPA16(smb + OAL * 2 + aDst, aSrcL);
            CPA16(smb + OBH * 2 + bDst, bSrcH);
            CPA16(smb + OBL * 2 + bDst, bSrcL);
            CPA_COMMIT();

            #pragma unroll 1
            for (int i = 0; i < 16; i++) {
                CPA_WAIT0();
                __syncthreads();
                if (i < 15) {
                    uint32_t sb1 = smb + ((i + 1) & 1) * (ST_H * 2);
                    int kc = (i + 1) * 32;
                    CPA16(sb1 + OAH * 2 + aDst, aSrcH + kc);
                    CPA16(sb1 + OAL * 2 + aDst, aSrcL + kc);
                    CPA16(sb1 + OBH * 2 + bDst, bSrcH + kc * 1024);
                    CPA16(sb1 + OBL * 2 + bDst, bSrcL + kc * 1024);
                    CPA_COMMIT();
                }
                uint32_t sb = smb + (i & 1) * (ST_H * 2);
                #pragma unroll
                for (int kk = 0; kk < 2; kk++) {
                    uint32_t ako = kk * 32;
                    uint32_t bko = kk * 16 * (BP * 2);
                    uint32_t ah[4], al[4];
                    LDMX4(ah, sb + aoffH + ako);
                    LDMX4(al, sb + aoffL + ako);
                    #pragma unroll
                    for (int ng = 0; ng < 2; ng++) {
                        uint32_t bh[4], bl[4];
                        LDMX4T(bh, sb + boffH[ng] + bko);
                        LDMX4T(bl, sb + boffL[ng] + bko);
                        MMA16(acc[ng * 2],     ah, bh[0], bh[1]);
                        MMA16(acc[ng * 2],     ah, bl[0], bl[1]);
                        MMA16(acc[ng * 2],     al, bh[0], bh[1]);
                        MMA16(acc[ng * 2 + 1], ah, bh[2], bh[3]);
                        MMA16(acc[ng * 2 + 1], ah, bl[2], bl[3]);
                        MMA16(acc[ng * 2 + 1], al, bh[2], bh[3]);
                    }
                }
            }
            float* dst = kz ? g_z1 : out;
            int g = lane >> 2, q = lane & 3;
            int row = m0 + mbase + g;
            #pragma unroll
            for (int n8 = 0; n8 < 4; n8++) {
                int col = n0 + nbase + n8 * 8 + 2 * q;
                *(float2*)(dst + row * 1024 + col)       = make_float2(acc[n8][0], acc[n8][1]);
                *(float2*)(dst + (row + 8) * 1024 + col) = make_float2(acc[n8][2], acc[n8][3]);
            }
        }
    }
    gsync(3);

    // ================= P5: split-K sum + instance norm + leaky relu
    for (int o = bid; o < 512; o += NB) {
        __syncthreads();
        float4* row = (float4*)(out + o * 1024);
        const float4* row1 = (const float4*)(g_z1 + o * 1024);
        float4 v = row[t];
        float4 v1 = row1[t];
        v.x += v1.x; v.y += v1.y; v.z += v1.z; v.w += v1.w;
        float s = v.x + v.y + v.z + v.w;
        float ss = v.x * v.x + v.y * v.y + v.z * v.z + v.w * v.w;
        #pragma unroll
        for (int off2 = 16; off2; off2 >>= 1) {
            s  += __shfl_down_sync(0xffffffffu, s, off2);
            ss += __shfl_down_sync(0xffffffffu, ss, off2);
        }
        if (lane == 0) { s_red[w] = s; s_red2[w] = ss; }
        __syncthreads();
        if (t == 0) {
            float ts = 0.f, tss = 0.f;
            #pragma unroll
            for (int i = 0; i < 8; i++) { ts += s_red[i]; tss += s_red2[i]; }
            float mu = ts * (1.f / 1024.f);
            float var = tss * (1.f / 1024.f) - mu * mu;
            s_mean = mu;
            s_inv = 1.f / sqrtf(var + 1e-5f);
        }
        __syncthreads();
        float mu = s_mean, inv = s_inv;
        float a;
        a = (v.x - mu) * inv; v.x = a >= 0.f ? a : 0.2f * a;
        a = (v.y - mu) * inv; v.y = a >= 0.f ? a : 0.2f * a;
        a = (v.z - mu) * inv; v.z = a >= 0.f ? a : 0.2f * a;
        a = (v.w - mu) * inv; v.w = a >= 0.f ? a : 0.2f * a;
        row[t] = v;
    }
}

// ---------------- launch ----------------
extern "C" void kernel_launch(void* const* d_in, const int* in_sizes, int n_in,
                              void* d_out, int out_size) {
    const float* x  = (const float*)d_in[0];   // (1,512,32,32)
    const float* w1 = (const float*)d_in[1];   // (32,512)
    const float* b1 = (const float*)d_in[2];   // (32)
    const float* w2 = (const float*)d_in[3];   // (512,32)
    const float* b2 = (const float*)d_in[4];   // (512)
    const float* dw = (const float*)d_in[5];   // (512,1024)
    float* out = (float*)d_out;                // (1,512,32,32) fp32

    k_mega<<<NB, 256>>>(x, w1, b1, w2, b2, dw, out);
}

// round 14
// speedup vs baseline: 1.0456x; 1.0456x over previous
#include <cuda_runtime.h>
#include <cuda_fp16.h>
#include <stdint.h>
#include <math.h>

#define NB 296   // 2 blocks/SM on 148 SMs — guaranteed co-resident (regs<=128, smem 41KB)

// ---------------- scratch (no allocations allowed) ----------------
__device__ float g_y[512];                  // channel means
__device__ float g_A[32 * 32];              // gaussian matrix A[i][x]
__device__ float g_f0t[1024 * 512];         // f0 transposed: [pix][ch]
__device__ float g_sigt[1024 * 512];        // sigmoid(f0): [pix][ch]
__device__ __half g_Wh[512 * 1024];         // W fp16 hi
__device__ __half g_Wl[512 * 1024];         // W fp16 residual
__device__ __half g_ch[1024 * 1024];        // cat fp16 hi, natural flat [i][p]
__device__ __half g_cl[1024 * 1024];        // cat fp16 residual
__device__ float g_z1[512 * 1024];          // split-K half-1 partial
__device__ unsigned g_arrive[8];            // grid barrier tickets (monotonic)

// ---------------- helpers ----------------
__device__ __forceinline__ uint32_t smem_u32(const void* p) {
    uint32_t a;
    asm("{ .reg .u64 t; cvta.to.shared.u64 t, %1; cvt.u32.u64 %0, t; }" : "=r"(a) : "l"(p));
    return a;
}
#define CPA16(sm, g) asm volatile("cp.async.ca.shared.global [%0], [%1], 16;" :: "r"(sm), "l"(g))
#define CPA_COMMIT()  asm volatile("cp.async.commit_group;" ::: "memory")
#define CPA_WAIT0()   asm volatile("cp.async.wait_group 0;" ::: "memory")
#define LDMX4(r, a) \
    asm volatile("ldmatrix.sync.aligned.m8n8.x4.shared.b16 {%0,%1,%2,%3}, [%4];" \
                 : "=r"((r)[0]), "=r"((r)[1]), "=r"((r)[2]), "=r"((r)[3]) : "r"(a))
#define LDMX4T(r, a) \
    asm volatile("ldmatrix.sync.aligned.m8n8.x4.trans.shared.b16 {%0,%1,%2,%3}, [%4];" \
                 : "=r"((r)[0]), "=r"((r)[1]), "=r"((r)[2]), "=r"((r)[3]) : "r"(a))
#define MMA16(d, a, b0v, b1v) \
    asm volatile("mma.sync.aligned.m16n8k16.row.col.f32.f16.f16.f32 " \
                 "{%0,%1,%2,%3},{%4,%5,%6,%7},{%8,%9},{%0,%1,%2,%3};" \
                 : "+f"((d)[0]), "+f"((d)[1]), "+f"((d)[2]), "+f"((d)[3]) \
                 : "r"((a)[0]), "r"((a)[1]), "r"((a)[2]), "r"((a)[3]), "r"(b0v), "r"(b1v))

__device__ __forceinline__ void split_h(float f, __half& h, __half& l) {
    h = __float2half_rn(f);
    l = __float2half_rn(f - __half2float(h));
}

// GEMM smem geometry
#define AP 40
#define BP 72
#define A_PLANE (64 * AP)
#define B_PLANE (32 * BP)
#define ST_H (2 * A_PLANE + 2 * B_PLANE)   // 9728 halves / stage
#define OAH 0
#define OAL A_PLANE
#define OBH (2 * A_PLANE)
#define OBL (2 * A_PLANE + B_PLANE)

// grid barrier: monotonic tickets, replay-safe, no resets
__device__ __forceinline__ void gsync(int k) {
    __syncthreads();
    __threadfence();
    if (threadIdx.x == 0) {
        unsigned ticket = atomicAdd(&g_arrive[k], 1u);
        unsigned target = (ticket / NB + 1u) * NB;
        while (*(volatile unsigned*)&g_arrive[k] < target) { __nanosleep(64); }
    }
    __syncthreads();
    __threadfence();
}

__global__ void __launch_bounds__(256, 2) k_mega(
    const float* __restrict__ x,  const float* __restrict__ w1,
    const float* __restrict__ b1, const float* __restrict__ w2,
    const float* __restrict__ b2, const float* __restrict__ dw,
    float* __restrict__ out)
{
    __shared__ __align__(16) char u_smem[2 * ST_H * 2];   // 38912 B union buffer
    __shared__ float s_scale[512];
    __shared__ float s_hidden[32];
    __shared__ double s_srow[32];
    __shared__ float s_red[8], s_red2[8];
    __shared__ float s_wsum[8][9], s_sa[9];
    __shared__ float s_mean, s_inv;

    int t = threadIdx.x, bid = blockIdx.x;
    int lane = t & 31, w = t >> 5;

    // ================= P0: means (0-511) + gaussian A (512) + W split (513-1024)
    for (int job = bid; job < 1025; job += NB) {
        __syncthreads();
        if (job < 512) {
            int c = job;
            float4 v = ((const float4*)(x + c * 1024))[t];
            float s = v.x + v.y + v.z + v.w;
            #pragma unroll
            for (int o = 16; o; o >>= 1) s += __shfl_down_sync(0xffffffffu, s, o);
            if (lane == 0) s_red[w] = s;
            __syncthreads();
            if (t == 0) {
                float tot = 0.f;
                #pragma unroll
                for (int i = 0; i < 8; i++) tot += s_red[i];
                g_y[c] = tot * (1.f / 1024.f);
            }
        } else if (job == 512) {
            if (t < 32) {
                double s = 0.0;
                for (int xx = 0; xx < 32; xx++) {
                    double d = (double)(xx - t);
                    s += exp(-d * d / 4.5);
                }
                s_srow[t] = s;
            }
            __syncthreads();
            for (int idx = t; idx < 1024; idx += 256) {
                int i = idx >> 5, xx = idx & 31;
                double d = (double)(xx - i);
                g_A[idx] = (float)(exp(-d * d / 4.5) / s_srow[i]);
            }
        } else {
            int row = job - 513;   // 0..511
            #pragma unroll
            for (int j = 0; j < 4; j++) {
                int idx = row * 1024 + t + j * 256;
                __half h, l;
                split_h(dw[idx], h, l);
                g_Wh[idx] = h;
                g_Wl[idx] = l;
            }
        }
    }
    gsync(0);

    // ================= P1: SE MLP, redundantly per block -> s_scale
    {
        for (int u = w; u < 32; u += 8) {
            float a = 0.f;
            for (int c = lane; c < 512; c += 32) a += g_y[c] * w1[u * 512 + c];
            #pragma unroll
            for (int o = 16; o; o >>= 1) a += __shfl_down_sync(0xffffffffu, a, o);
            if (lane == 0) s_hidden[u] = fmaxf(a + b1[u], 0.f);
        }
        __syncthreads();
        for (int c = t; c < 512; c += 256) {
            float acc = b2[c];
            #pragma unroll
            for (int rr = 0; rr < 32; rr++) acc += s_hidden[rr] * w2[c * 32 + rr];
            s_scale[c] = 1.f / (1.f + expf(-acc));
        }
        __syncthreads();
    }

    // ================= P2: gauss (0-511) + scale/transpose/sigmoid (512-1023)
    for (int job = bid; job < 1024; job += NB) {
        __syncthreads();
        float* sbuf = (float*)u_smem;
        if (job < 512) {
            float* F   = sbuf;
            float* T   = sbuf + 1024;
            float* sA  = sbuf + 2048;
            float* sAt = sbuf + 3072;
            int c = job;
            float s = s_scale[c];
            for (int i = t; i < 1024; i += 256) {
                F[i] = x[c * 1024 + i] * s;
                float a = g_A[i];
                sA[i] = a;
                sAt[(i & 31) * 32 + (i >> 5)] = a;
            }
            __syncthreads();
            for (int idx = t; idx < 1024; idx += 256) {   // T[x][k] = sum_y A[k][y]*F[x][y]
                int xx = idx >> 5, k = idx & 31;
                float acc = 0.f;
                #pragma unroll
                for (int y = 0; y < 32; y++) acc += sAt[y * 32 + k] * F[xx * 32 + y];
                T[idx] = acc;
            }
            __syncthreads();
            for (int idx = t; idx < 1024; idx += 256) {   // B[i][k] = sum_x A[i][x]*T[x][k]
                int i = idx >> 5, k = idx & 31;
                float acc = 0.f;
                #pragma unroll
                for (int xx = 0; xx < 32; xx++) acc += sA[i * 32 + xx] * T[xx * 32 + k];
                int f = idx * 512 + c;
                __half h, l;
                split_h(acc, h, l);
                g_ch[f] = h;
                g_cl[f] = l;
            }
        } else {
            float (*tile)[33] = (float(*)[33])sbuf;
            int bid2 = job - 512;
            int p0 = (bid2 & 31) * 32, c0 = (bid2 >> 5) * 32;
            int tx = lane, ty = w;
            #pragma unroll
            for (int j = 0; j < 4; j++) {
                int ch = c0 + ty + j * 8;
                tile[ty + j * 8][tx] = x[ch * 1024 + p0 + tx] * s_scale[ch];
            }
            __syncthreads();
            #pragma unroll
            for (int j = 0; j < 4; j++) {
                int p = p0 + ty + j * 8;
                float v = tile[tx][ty + j * 8];
                g_f0t[p * 512 + c0 + tx] = v;
                g_sigt[p * 512 + c0 + tx] = 1.f / (1.f + expf(-v));
            }
        }
    }
    gsync(1);

    // ================= P3: 3x3 patch-correlation attention
    for (int pix = bid; pix < 1024; pix += NB) {
        __syncthreads();
        int pi = pix >> 5, pj = pix & 31;
        int base = pix * 512 + t;
        float sc0 = g_sigt[base];
        float sc1 = g_sigt[base + 256];
        bool okU = pi > 0, okD = pi < 31, okL = pj > 0, okR = pj < 31;
        bool ok[9];
        ok[0] = okU && okL; ok[1] = okU; ok[2] = okU && okR;
        ok[3] = okL;        ok[4] = true; ok[5] = okR;
        ok[6] = okD && okL; ok[7] = okD; ok[8] = okD && okR;
        const int off[9] = { -33*512, -32*512, -31*512, -1*512, 0, 1*512, 31*512, 32*512, 33*512 };
        float acc[9];
        #pragma unroll
        for (int uv = 0; uv < 9; uv++) {
            acc[uv] = ok[uv]
                ? sc0 * g_sigt[base + off[uv]] + sc1 * g_sigt[base + off[uv] + 256]
                : 0.f;
        }
        #pragma unroll
        for (int uv = 0; uv < 9; uv++)
            #pragma unroll
            for (int o = 16; o; o >>= 1) acc[uv] += __shfl_down_sync(0xffffffffu, acc[uv], o);
        if (lane == 0) {
            #pragma unroll
            for (int uv = 0; uv < 9; uv++) s_wsum[w][uv] = acc[uv];
        }
        __syncthreads();
        if (t < 32) {
            float v = -1e30f;
            if (t < 9) {
                float s2 = 0.f;
                #pragma unroll
                for (int ww = 0; ww < 8; ww++) s2 += s_wsum[ww][t];
                v = s2 * (1.f / 512.f);
            }
            float m = v;
            #pragma unroll
            for (int o = 16; o; o >>= 1) m = fmaxf(m, __shfl_xor_sync(0xffffffffu, m, o));
            float e = (t < 9) ? expf(v - m) : 0.f;
            float tot = e;
            #pragma unroll
            for (int o = 16; o; o >>= 1) tot += __shfl_xor_sync(0xffffffffu, tot, o);
            if (t < 9) s_sa[t] = e / tot;
        }
        __syncthreads();
        float o0 = 0.f, o1 = 0.f;
        #pragma unroll
        for (int uv = 0; uv < 9; uv++) {
            if (ok[uv]) {
                float a = s_sa[uv];
                o0 += a * g_f0t[base + off[uv]];
                o1 += a * g_f0t[base + off[uv] + 256];
            }
        }
        __half h, l;
        split_h(o0, h, l); g_ch[524288 + base] = h;       g_cl[524288 + base] = l;
        split_h(o1, h, l); g_ch[524288 + base + 256] = h; g_cl[524288 + base + 256] = l;
    }
    gsync(2);

    // ================= P4: GEMM tiles (fp16-split mma.sync, split-K=2, 256 tiles)
    {
        __half* sm = (__half*)u_smem;
        uint32_t smb = smem_u32(sm);
        int mbase = (w >> 1) * 16, nbase = (w & 1) * 32;
        int arow = t >> 2, aseg = t & 3;
        int brow = t >> 3, bseg = t & 7;
        uint32_t aDst = arow * (AP * 2) + aseg * 16;
        uint32_t bDst = brow * (BP * 2) + bseg * 16;
        int ar = lane & 7, ah8 = (lane >> 3) & 1, akh = lane >> 4;
        uint32_t aoffH = OAH * 2 + (mbase + ah8 * 8 + ar) * (AP * 2) + akh * 16;
        uint32_t aoffL = OAL * 2 + (mbase + ah8 * 8 + ar) * (AP * 2) + akh * 16;
        int br = lane & 7, bk8 = (lane >> 3) & 1, bn8 = lane >> 4;
        uint32_t boffH[2], boffL[2];
        #pragma unroll
        for (int ng = 0; ng < 2; ng++) {
            uint32_t col2 = (nbase + ng * 16 + bn8 * 8) * 2;
            boffH[ng] = OBH * 2 + (bk8 * 8 + br) * (BP * 2) + col2;
            boffL[ng] = OBL * 2 + (bk8 * 8 + br) * (BP * 2) + col2;
        }

        for (int tile = bid; tile < 256; tile += NB) {
            __syncthreads();
            int nx = tile & 15, my = (tile >> 4) & 7, kz = tile >> 7;
            int m0 = my * 64, n0 = nx * 64, kbase = kz * 512;
            const __half* aSrcH = g_Wh + (m0 + arow) * 1024 + kbase + aseg * 8;
            const __half* aSrcL = g_Wl + (m0 + arow) * 1024 + kbase + aseg * 8;
            const __half* bSrcH = g_ch + (kbase + brow) * 1024 + n0 + bseg * 8;
            const __half* bSrcL = g_cl + (kbase + brow) * 1024 + n0 + bseg * 8;

            float acc[4][4] = {};
            CPA16(smb + OAH * 2 + aDst, aSrcH);
            CPA16(smb + OAL * 2 + aDst, aSrcL);
            CPA16(smb + OBH * 2 + bDst, bSrcH);
            CPA16(smb + OBL * 2 + bDst, bSrcL);
            CPA_COMMIT();

            #pragma unroll 1
            for (int i = 0; i < 16; i++) {
                CPA_WAIT0();
                __syncthreads();
                if (i < 15) {
                    uint32_t sb1 = smb + ((i + 1) & 1) * (ST_H * 2);
                    int kc = (i + 1) * 32;
                    CPA16(sb1 + OAH * 2 + aDst, aSrcH + kc);
                    CPA16(sb1 + OAL * 2 + aDst, aSrcL + kc);
                    CPA16(sb1 + OBH * 2 + bDst, bSrcH + kc * 1024);
                    CPA16(sb1 + OBL * 2 + bDst, bSrcL + kc * 1024);
                    CPA_COMMIT();
                }
                uint32_t sb = smb + (i & 1) * (ST_H * 2);
                #pragma unroll
                for (int kk = 0; kk < 2; kk++) {
                    uint32_t ako = kk * 32;
                    uint32_t bko = kk * 16 * (BP * 2);
                    uint32_t ah[4], al[4];
                    LDMX4(ah, sb + aoffH + ako);
                    LDMX4(al, sb + aoffL + ako);
                    #pragma unroll
                    for (int ng = 0; ng < 2; ng++) {
                        uint32_t bh[4], bl[4];
                        LDMX4T(bh, sb + boffH[ng] + bko);
                        LDMX4T(bl, sb + boffL[ng] + bko);
                        MMA16(acc[ng * 2],     ah, bh[0], bh[1]);
                        MMA16(acc[ng * 2],     ah, bl[0], bl[1]);
                        MMA16(acc[ng * 2],     al, bh[0], bh[1]);
                        MMA16(acc[ng * 2 + 1], ah, bh[2], bh[3]);
                        MMA16(acc[ng * 2 + 1], ah, bl[2], bl[3]);
                        MMA16(acc[ng * 2 + 1], al, bh[2], bh[3]);
                    }
                }
            }
            float* dst = kz ? g_z1 : out;
            int g = lane >> 2, q = lane & 3;
            int row = m0 + mbase + g;
            #pragma unroll
            for (int n8 = 0; n8 < 4; n8++) {
                int col = n0 + nbase + n8 * 8 + 2 * q;
                *(float2*)(dst + row * 1024 + col)       = make_float2(acc[n8][0], acc[n8][1]);
                *(float2*)(dst + (row + 8) * 1024 + col) = make_float2(acc[n8][2], acc[n8][3]);
            }
        }
    }
    gsync(3);

    // ================= P5: split-K sum + instance norm + leaky relu
    for (int o = bid; o < 512; o += NB) {
        __syncthreads();
        float4* row = (float4*)(out + o * 1024);
        const float4* row1 = (const float4*)(g_z1 + o * 1024);
        float4 v = row[t];
        float4 v1 = row1[t];
        v.x += v1.x; v.y += v1.y; v.z += v1.z; v.w += v1.w;
        float s = v.x + v.y + v.z + v.w;
        float ss = v.x * v.x + v.y * v.y + v.z * v.z + v.w * v.w;
        #pragma unroll
        for (int off2 = 16; off2; off2 >>= 1) {
            s  += __shfl_down_sync(0xffffffffu, s, off2);
            ss += __shfl_down_sync(0xffffffffu, ss, off2);
        }
        if (lane == 0) { s_red[w] = s; s_red2[w] = ss; }
        __syncthreads();
        if (t == 0) {
            float ts = 0.f, tss = 0.f;
            #pragma unroll
            for (int i = 0; i < 8; i++) { ts += s_red[i]; tss += s_red2[i]; }
            float mu = ts * (1.f / 1024.f);
            float var = tss * (1.f / 1024.f) - mu * mu;
            s_mean = mu;
            s_inv = 1.f / sqrtf(var + 1e-5f);
        }
        __syncthreads();
        float mu = s_mean, inv = s_inv;
        float a;
        a = (v.x - mu) * inv; v.x = a >= 0.f ? a : 0.2f * a;
        a = (v.y - mu) * inv; v.y = a >= 0.f ? a : 0.2f * a;
        a = (v.z - mu) * inv; v.z = a >= 0.f ? a : 0.2f * a;
        a = (v.w - mu) * inv; v.w = a >= 0.f ? a : 0.2f * a;
        row[t] = v;
    }
}

// ---------------- launch ----------------
extern "C" void kernel_launch(void* const* d_in, const int* in_sizes, int n_in,
                              void* d_out, int out_size) {
    const float* x  = (const float*)d_in[0];   // (1,512,32,32)
    const float* w1 = (const float*)d_in[1];   // (32,512)
    const float* b1 = (const float*)d_in[2];   // (32)
    const float* w2 = (const float*)d_in[3];   // (512,32)
    const float* b2 = (const float*)d_in[4];   // (512)
    const float* dw = (const float*)d_in[5];   // (512,1024)
    float* out = (float*)d_out;                // (1,512,32,32) fp32

    k_mega<<<NB, 256>>>(x, w1, b1, w2, b2, dw, out);
}

// round 15
// speedup vs baseline: 1.2646x; 1.2095x over previous
#include <cuda_runtime.h>
#include <cuda_fp16.h>
#include <stdint.h>
#include <math.h>

#define NC 512
#define NPIX 1024

// ---------------- scratch (no allocations allowed) ----------------
__device__ float g_y[NC];                   // channel means
__device__ float g_s[NC];                   // SE scales
__device__ float g_A[32 * 32];              // gaussian matrix A[i][x]
__device__ float g_f0t[NPIX * NC];          // f0 transposed: [pix][ch]
__device__ float g_sigt[NPIX * NC];         // sigmoid(f0): [pix][ch]
__device__ __half g_Wh[NC * 1024];          // W fp16 hi, [o][i] k-major
__device__ __half g_Wl[NC * 1024];          // W fp16 residual
__device__ __half g_ch[1024 * 1024];        // cat fp16 hi, natural flat layout [i][p]
__device__ __half g_cl[1024 * 1024];        // cat fp16 residual
__device__ float g_z1[NC * NPIX];           // split-K half-1 partial

// ---------------- helpers ----------------
__device__ __forceinline__ uint32_t smem_u32(const void* p) {
    uint32_t a;
    asm("{ .reg .u64 t; cvta.to.shared.u64 t, %1; cvt.u32.u64 %0, t; }" : "=r"(a) : "l"(p));
    return a;
}
#define CPA16(sm, g) asm volatile("cp.async.ca.shared.global [%0], [%1], 16;" :: "r"(sm), "l"(g))
#define CPA_COMMIT()  asm volatile("cp.async.commit_group;" ::: "memory")
#define CPA_WAIT0()   asm volatile("cp.async.wait_group 0;" ::: "memory")

#define LDMX4(r, a) \
    asm volatile("ldmatrix.sync.aligned.m8n8.x4.shared.b16 {%0,%1,%2,%3}, [%4];" \
                 : "=r"((r)[0]), "=r"((r)[1]), "=r"((r)[2]), "=r"((r)[3]) : "r"(a))
#define LDMX4T(r, a) \
    asm volatile("ldmatrix.sync.aligned.m8n8.x4.trans.shared.b16 {%0,%1,%2,%3}, [%4];" \
                 : "=r"((r)[0]), "=r"((r)[1]), "=r"((r)[2]), "=r"((r)[3]) : "r"(a))

#define MMA16(d, a, b0v, b1v) \
    asm volatile("mma.sync.aligned.m16n8k16.row.col.f32.f16.f16.f32 " \
                 "{%0,%1,%2,%3},{%4,%5,%6,%7},{%8,%9},{%0,%1,%2,%3};" \
                 : "+f"((d)[0]), "+f"((d)[1]), "+f"((d)[2]), "+f"((d)[3]) \
                 : "r"((a)[0]), "r"((a)[1]), "r"((a)[2]), "r"((a)[3]), "r"(b0v), "r"(b1v))

__device__ __forceinline__ void split_h(float f, __half& h, __half& l) {
    h = __float2half_rn(f);
    l = __float2half_rn(f - __half2float(h));
}

// ---------------- 1. per-channel mean (0..511) + gaussian A (512) + W fp16-split (513..1024) ----------------
__global__ void k_mean_initA(const float* __restrict__ x, const float* __restrict__ dw) {
    int t = threadIdx.x;
    if (blockIdx.x < 512) {
        int c = blockIdx.x;
        float4 v = ((const float4*)(x + c * 1024))[t];
        float s = v.x + v.y + v.z + v.w;
        #pragma unroll
        for (int o = 16; o; o >>= 1) s += __shfl_down_sync(0xffffffffu, s, o);
        __shared__ float ws[8];
        if ((t & 31) == 0) ws[t >> 5] = s;
        __syncthreads();
        if (t == 0) {
            float tot = 0.f;
            #pragma unroll
            for (int i = 0; i < 8; i++) tot += ws[i];
            g_y[c] = tot * (1.f / 1024.f);
        }
    } else if (blockIdx.x == 512) {
        __shared__ double srow[32];
        if (t < 32) {
            double s = 0.0;
            for (int xx = 0; xx < 32; xx++) {
                double d = (double)(xx - t);
                s += exp(-d * d / 4.5);
            }
            srow[t] = s;
        }
        __syncthreads();
        for (int idx = t; idx < 1024; idx += 256) {
            int i = idx >> 5, xx = idx & 31;
            double d = (double)(xx - i);
            g_A[idx] = (float)(exp(-d * d / 4.5) / srow[i]);
        }
    } else {
        int row = blockIdx.x - 513;   // 0..511
        #pragma unroll
        for (int j = 0; j < 4; j++) {
            int idx = row * 1024 + t + j * 256;
            __half h, l;
            split_h(dw[idx], h, l);
            g_Wh[idx] = h;
            g_Wl[idx] = l;
        }
    }
}

// ---------------- 2. SE MLP: 512 -> 32 (relu) -> 512 (sigmoid) ----------------
__global__ void k_mlp(const float* __restrict__ w1, const float* __restrict__ b1,
                      const float* __restrict__ w2, const float* __restrict__ b2) {
    __shared__ float sy[512];
    __shared__ float sh[32];
    int t = threadIdx.x;
    if (t < 512) sy[t] = g_y[t];
    __syncthreads();
    int r = t >> 5, lane = t & 31;
    float a = 0.f;
    for (int c = lane; c < 512; c += 32) a += sy[c] * w1[r * 512 + c];
    #pragma unroll
    for (int o = 16; o; o >>= 1) a += __shfl_down_sync(0xffffffffu, a, o);
    if (lane == 0) sh[r] = fmaxf(a + b1[r], 0.f);
    __syncthreads();
    if (t < 512) {
        float acc = b2[t];
        #pragma unroll
        for (int rr = 0; rr < 32; rr++) acc += sh[rr] * w2[t * 32 + rr];
        g_s[t] = 1.f / (1.f + expf(-acc));
    }
}

// ---------------- 3. fused: gaussian pooling (0..511) + scale/transpose/sigmoid (512..1023) ----------------
__global__ void k_gauss_trans(const float* __restrict__ x) {
    __shared__ float sbuf[4096];
    int t = threadIdx.x;
    if (blockIdx.x < 512) {
        float* F   = sbuf;
        float* T   = sbuf + 1024;
        float* sA  = sbuf + 2048;
        float* sAt = sbuf + 3072;
        int c = blockIdx.x;
        float s = g_s[c];
        for (int i = t; i < 1024; i += 256) {
            F[i] = x[c * 1024 + i] * s;
            float a = g_A[i];
            sA[i] = a;
            sAt[(i & 31) * 32 + (i >> 5)] = a;
        }
        __syncthreads();
        for (int idx = t; idx < 1024; idx += 256) {   // T[x][k] = sum_y A[k][y]*F[x][y]
            int xx = idx >> 5, k = idx & 31;
            float acc = 0.f;
            #pragma unroll
            for (int y = 0; y < 32; y++) acc += sAt[y * 32 + k] * F[xx * 32 + y];
            T[idx] = acc;
        }
        __syncthreads();
        for (int idx = t; idx < 1024; idx += 256) {   // B[i][k] = sum_x A[i][x]*T[x][k]
            int i = idx >> 5, k = idx & 31;
            float acc = 0.f;
            #pragma unroll
            for (int xx = 0; xx < 32; xx++) acc += sA[i * 32 + xx] * T[xx * 32 + k];
            int f = idx * 512 + c;                    // flat cat index (natural layout)
            __half h, l;
            split_h(acc, h, l);
            g_ch[f] = h;
            g_cl[f] = l;
        }
    } else {
        float (*tile)[33] = (float(*)[33])sbuf;
        int bid = blockIdx.x - 512;
        int p0 = (bid & 31) * 32, c0 = (bid >> 5) * 32;
        int tx = t & 31, ty = t >> 5;
        #pragma unroll
        for (int j = 0; j < 4; j++) {
            int ch = c0 + ty + j * 8;
            tile[ty + j * 8][tx] = x[ch * 1024 + p0 + tx] * g_s[ch];
        }
        __syncthreads();
        #pragma unroll
        for (int j = 0; j < 4; j++) {
            int p = p0 + ty + j * 8;
            float v = tile[tx][ty + j * 8];
            g_f0t[p * 512 + c0 + tx] = v;
            g_sigt[p * 512 + c0 + tx] = 1.f / (1.f + expf(-v));
        }
    }
}

// ---------------- 4. 3x3 patch-correlation attention (R11 two-gather form) ----------------
__global__ void k_csa() {
    int pix = blockIdx.x, pi = pix >> 5, pj = pix & 31;
    int t = threadIdx.x;
    int base = pix * 512 + t;
    __shared__ float wsum[8][9];
    __shared__ float sa[9];

    float sc0 = g_sigt[base];
    float sc1 = g_sigt[base + 256];

    bool okU = pi > 0, okD = pi < 31, okL = pj > 0, okR = pj < 31;
    bool ok[9];
    ok[0] = okU && okL; ok[1] = okU; ok[2] = okU && okR;
    ok[3] = okL;        ok[4] = true; ok[5] = okR;
    ok[6] = okD && okL; ok[7] = okD; ok[8] = okD && okR;
    const int off[9] = { -33*512, -32*512, -31*512, -1*512, 0, 1*512, 31*512, 32*512, 33*512 };

    float acc[9];
    #pragma unroll
    for (int uv = 0; uv < 9; uv++) {
        acc[uv] = ok[uv]
            ? sc0 * g_sigt[base + off[uv]] + sc1 * g_sigt[base + off[uv] + 256]
            : 0.f;
    }
    #pragma unroll
    for (int uv = 0; uv < 9; uv++)
        #pragma unroll
        for (int o = 16; o; o >>= 1) acc[uv] += __shfl_down_sync(0xffffffffu, acc[uv], o);
    if ((t & 31) == 0) {
        #pragma unroll
        for (int uv = 0; uv < 9; uv++) wsum[t >> 5][uv] = acc[uv];
    }
    __syncthreads();
    if (t < 32) {
        float v = -1e30f;
        if (t < 9) {
            float s2 = 0.f;
            #pragma unroll
            for (int w = 0; w < 8; w++) s2 += wsum[w][t];
            v = s2 * (1.f / 512.f);
        }
        float m = v;
        #pragma unroll
        for (int o = 16; o; o >>= 1) m = fmaxf(m, __shfl_xor_sync(0xffffffffu, m, o));
        float e = (t < 9) ? expf(v - m) : 0.f;
        float tot = e;
        #pragma unroll
        for (int o = 16; o; o >>= 1) tot += __shfl_xor_sync(0xffffffffu, tot, o);
        if (t < 9) sa[t] = e / tot;
    }
    __syncthreads();

    float o0 = 0.f, o1 = 0.f;
    #pragma unroll
    for (int uv = 0; uv < 9; uv++) {
        if (ok[uv]) {
            float a = sa[uv];
            o0 += a * g_f0t[base + off[uv]];
            o1 += a * g_f0t[base + off[uv] + 256];
        }
    }
    __half h, l;
    split_h(o0, h, l); g_ch[524288 + base] = h;       g_cl[524288 + base] = l;
    split_h(o1, h, l); g_ch[524288 + base + 256] = h; g_cl[524288 + base + 256] = l;
}

// ---------------- 5. down GEMM: fp16-split mma.sync, split-K=2, B via ldmatrix.trans ----------------
#define AP 40                     // A pitch (halves)
#define BP 72                     // B pitch (halves)
#define A_PLANE (64 * AP)
#define B_PLANE (32 * BP)
#define ST_H (2 * A_PLANE + 2 * B_PLANE)
#define OAH 0
#define OAL A_PLANE
#define OBH (2 * A_PLANE)
#define OBL (2 * A_PLANE + B_PLANE)

__global__ void __launch_bounds__(256) k_gemm(float* __restrict__ out) {
    __shared__ __align__(16) __half sm[2 * ST_H];
    int t = threadIdx.x, lane = t & 31, w = t >> 5;
    int mbase = (w >> 1) * 16, nbase = (w & 1) * 32;
    int m0 = blockIdx.y * 64, n0 = blockIdx.x * 64;
    int kbase = blockIdx.z * 512;
    uint32_t smb = smem_u32(sm);

    int arow = t >> 2, aseg = t & 3;
    int brow = t >> 3, bseg = t & 7;
    const __half* aSrcH = g_Wh + (m0 + arow) * 1024 + kbase + aseg * 8;
    const __half* aSrcL = g_Wl + (m0 + arow) * 1024 + kbase + aseg * 8;
    const __half* bSrcH = g_ch + (kbase + brow) * 1024 + n0 + bseg * 8;
    const __half* bSrcL = g_cl + (kbase + brow) * 1024 + n0 + bseg * 8;
    uint32_t aDst = arow * (AP * 2) + aseg * 16;
    uint32_t bDst = brow * (BP * 2) + bseg * 16;

    int ar = lane & 7, ah8 = (lane >> 3) & 1, akh = lane >> 4;
    uint32_t aoffH = OAH * 2 + (mbase + ah8 * 8 + ar) * (AP * 2) + akh * 16;
    uint32_t aoffL = OAL * 2 + (mbase + ah8 * 8 + ar) * (AP * 2) + akh * 16;
    int br = lane & 7, bk8 = (lane >> 3) & 1, bn8 = lane >> 4;
    uint32_t boffH[2], boffL[2];
    #pragma unroll
    for (int ng = 0; ng < 2; ng++) {
        uint32_t col2 = (nbase + ng * 16 + bn8 * 8) * 2;
        boffH[ng] = OBH * 2 + (bk8 * 8 + br) * (BP * 2) + col2;
        boffL[ng] = OBL * 2 + (bk8 * 8 + br) * (BP * 2) + col2;
    }

    float acc[4][4] = {};

    CPA16(smb + OAH * 2 + aDst, aSrcH);
    CPA16(smb + OAL * 2 + aDst, aSrcL);
    CPA16(smb + OBH * 2 + bDst, bSrcH);
    CPA16(smb + OBL * 2 + bDst, bSrcL);
    CPA_COMMIT();

    #pragma unroll 1
    for (int i = 0; i < 16; i++) {
        CPA_WAIT0();
        __syncthreads();
        if (i < 15) {
            uint32_t sb1 = smb + ((i + 1) & 1) * (ST_H * 2);
            int kc = (i + 1) * 32;
            CPA16(sb1 + OAH * 2 + aDst, aSrcH + kc);
            CPA16(sb1 + OAL * 2 + aDst, aSrcL + kc);
            CPA16(sb1 + OBH * 2 + bDst, bSrcH + kc * 1024);
            CPA16(sb1 + OBL * 2 + bDst, bSrcL + kc * 1024);
            CPA_COMMIT();
        }
        uint32_t sb = smb + (i & 1) * (ST_H * 2);
        #pragma unroll
        for (int kk = 0; kk < 2; kk++) {
            uint32_t ako = kk * 32;
            uint32_t bko = kk * 16 * (BP * 2);
            uint32_t ah[4], al[4];
            LDMX4(ah, sb + aoffH + ako);
            LDMX4(al, sb + aoffL + ako);
            #pragma unroll
            for (int ng = 0; ng < 2; ng++) {
                uint32_t bh[4], bl[4];
                LDMX4T(bh, sb + boffH[ng] + bko);
                LDMX4T(bl, sb + boffL[ng] + bko);
                MMA16(acc[ng * 2],     ah, bh[0], bh[1]);
                MMA16(acc[ng * 2],     ah, bl[0], bl[1]);
                MMA16(acc[ng * 2],     al, bh[0], bh[1]);
                MMA16(acc[ng * 2 + 1], ah, bh[2], bh[3]);
                MMA16(acc[ng * 2 + 1], ah, bl[2], bl[3]);
                MMA16(acc[ng * 2 + 1], al, bh[2], bh[3]);
            }
        }
    }
    float* dst = blockIdx.z ? g_z1 : out;
    int g = lane >> 2, q = lane & 3;
    int row = m0 + mbase + g;
    #pragma unroll
    for (int n8 = 0; n8 < 4; n8++) {
        int col = n0 + nbase + n8 * 8 + 2 * q;
        *(float2*)(dst + row * 1024 + col)       = make_float2(acc[n8][0], acc[n8][1]);
        *(float2*)(dst + (row + 8) * 1024 + col) = make_float2(acc[n8][2], acc[n8][3]);
    }
}

// ---------------- 6. split-K sum + instance norm + leaky relu ----------------
__global__ void k_norm(float* __restrict__ out) {
    int o = blockIdx.x, t = threadIdx.x;
    float4* row = (float4*)(out + o * 1024);
    const float4* row1 = (const float4*)(g_z1 + o * 1024);
    float4 v = row[t];
    float4 v1 = row1[t];
    v.x += v1.x; v.y += v1.y; v.z += v1.z; v.w += v1.w;
    float s = v.x + v.y + v.z + v.w;
    float ss = v.x * v.x + v.y * v.y + v.z * v.z + v.w * v.w;
    #pragma unroll
    for (int off = 16; off; off >>= 1) {
        s  += __shfl_down_sync(0xffffffffu, s, off);
        ss += __shfl_down_sync(0xffffffffu, ss, off);
    }
    __shared__ float w1s[8], w2s[8];
    __shared__ float smean, sinv;
    if ((t & 31) == 0) { w1s[t >> 5] = s; w2s[t >> 5] = ss; }
    __syncthreads();
    if (t == 0) {
        float ts = 0.f, tss = 0.f;
        #pragma unroll
        for (int i = 0; i < 8; i++) { ts += w1s[i]; tss += w2s[i]; }
        float mu = ts * (1.f / 1024.f);
        float var = tss * (1.f / 1024.f) - mu * mu;
        smean = mu;
        sinv = 1.f / sqrtf(var + 1e-5f);
    }
    __syncthreads();
    float mu = smean, inv = sinv;
    float a;
    a = (v.x - mu) * inv; v.x = a >= 0.f ? a : 0.2f * a;
    a = (v.y - mu) * inv; v.y = a >= 0.f ? a : 0.2f * a;
    a = (v.z - mu) * inv; v.z = a >= 0.f ? a : 0.2f * a;
    a = (v.w - mu) * inv; v.w = a >= 0.f ? a : 0.2f * a;
    row[t] = v;
}

// ---------------- launch ----------------
extern "C" void kernel_launch(void* const* d_in, const int* in_sizes, int n_in,
                              void* d_out, int out_size) {
    const float* x  = (const float*)d_in[0];   // (1,512,32,32)
    const float* w1 = (const float*)d_in[1];   // (32,512)
    const float* b1 = (const float*)d_in[2];   // (32)
    const float* w2 = (const float*)d_in[3];   // (512,32)
    const float* b2 = (const float*)d_in[4];   // (512)
    const float* dw = (const float*)d_in[5];   // (512,1024)
    float* out = (float*)d_out;                // (1,512,32,32) fp32

    k_mean_initA<<<1025, 256>>>(x, dw);
    k_mlp<<<1, 1024>>>(w1, b1, w2, b2);
    k_gauss_trans<<<1024, 256>>>(x);
    k_csa<<<1024, 256>>>();
    k_gemm<<<dim3(16, 8, 2), 256>>>(out);
    k_norm<<<512, 256>>>(out);
}